// round 1
// baseline (speedup 1.0000x reference)
#include <cuda_runtime.h>
#include <math.h>

#define NMAX 100000
#define EMAX 1600000
#define DD 64
#define NGR 16

// ---------------- device scratch ----------------
__device__ float g_y[(size_t)NMAX * DD];      // x @ Wm
__device__ float g_agg[(size_t)NMAX * DD];    // segment-max result
__device__ float g_feat[(size_t)NMAX * DD];   // lrelu(x @ Wfeat + bfeat)
__device__ float g_gate[NMAX];
__device__ int   g_deg[NMAX];
__device__ int   g_offs[NMAX];
__device__ int   g_cursor[NMAX];
__device__ int   g_src[EMAX];
__device__ int   g_counter;
__device__ float g_P[NGR * DD];               // x_global @ Wa_g
__device__ float g_numvec[NGR * DD];          // sum e*feat
__device__ float g_denom[NGR];                // sum e
__device__ int   g_gmax[NGR];                 // ordered-int float max

__device__ __forceinline__ float lrelu(float v) { return v > 0.f ? v : 0.01f * v; }
__device__ __forceinline__ int   ordInt(float f) { int i = __float_as_int(f); return i >= 0 ? i : i ^ 0x7FFFFFFF; }
__device__ __forceinline__ float ordFloat(int i) { return __int_as_float(i >= 0 ? i : i ^ 0x7FFFFFFF); }

// ---------------- setup kernels ----------------
__global__ void k_copy_init(const float* __restrict__ x, const float* __restrict__ xglob,
                            float* __restrict__ out, int N) {
    int i = blockIdx.x * blockDim.x + threadIdx.x;
    int nx = N * DD;
    int tot = nx + NGR * DD;
    if (i < nx) out[i] = x[i];
    else if (i < tot) out[i] = xglob[i - nx];
}

__global__ void k_csr_zero(int N) {
    int i = blockIdx.x * blockDim.x + threadIdx.x;
    if (i < N) { g_deg[i] = 0; g_cursor[i] = 0; }
    if (i == 0) g_counter = 0;
}

__global__ void k_deg(const int* __restrict__ ei, int E) {
    int e = blockIdx.x * blockDim.x + threadIdx.x;
    if (e < E) atomicAdd(&g_deg[ei[E + e]], 1);
}

__global__ void k_alloc(int N) {
    int n = blockIdx.x * blockDim.x + threadIdx.x;
    unsigned m = 0xffffffffu;
    int lane = threadIdx.x & 31;
    int d = (n < N) ? g_deg[n] : 0;
    int s = d;
#pragma unroll
    for (int o = 1; o < 32; o <<= 1) {
        int t = __shfl_up_sync(m, s, o);
        if (lane >= o) s += t;
    }
    int base = 0;
    if (lane == 31) base = atomicAdd(&g_counter, s);
    base = __shfl_sync(m, base, 31);
    if (n < N) g_offs[n] = base + s - d;
}

__global__ void k_fill(const int* __restrict__ ei, int E) {
    int e = blockIdx.x * blockDim.x + threadIdx.x;
    if (e >= E) return;
    int dst = ei[E + e];
    int p = atomicAdd(&g_cursor[dst], 1);
    g_src[g_offs[dst] + p] = ei[e];
}

// ---------------- per-step kernels ----------------
// P = x_global @ Wa_g ; reset gmax/denom/numvec. 1 block, 1024 threads.
__global__ void k_init_step(const float* __restrict__ xglob, const float* __restrict__ Wa_g) {
    int t = threadIdx.x;
    if (t < NGR) { g_denom[t] = 0.f; g_gmax[t] = ordInt(-INFINITY); }
    g_numvec[t] = 0.f;
    int g = t >> 6, c = t & 63;
    float s = 0.f;
#pragma unroll 8
    for (int k = 0; k < 64; k++) s = fmaf(xglob[g * 64 + k], Wa_g[k * 64 + c], s);
    g_P[t] = s;
}

// ---------------- GEMM core: 64-row x 64-col tile, K=64, 256 threads, 4x4 microtile
__device__ __forceinline__ void gemm_load(const float* __restrict__ A, const float* __restrict__ B,
                                          int row0, int N, float* As, float* Bs) {
    __syncthreads();  // protect smem from prior-phase readers
    int t = threadIdx.x;
#pragma unroll
    for (int it = 0; it < 4; it++) {
        int idx = t + it * 256;
        int r = idx >> 4, c4 = idx & 15;
        int gr = row0 + r;
        float4 v = make_float4(0.f, 0.f, 0.f, 0.f);
        if (gr < N) v = *(const float4*)(A + (size_t)gr * 64 + c4 * 4);
        *(float4*)(As + r * 64 + c4 * 4) = v;
        *(float4*)(Bs + r * 64 + c4 * 4) = *(const float4*)(B + r * 64 + c4 * 4);
    }
    __syncthreads();
}

__device__ __forceinline__ void gemm_compute(const float* As, const float* Bs,
                                             int tx, int ty, float acc[4][4]) {
#pragma unroll 16
    for (int k = 0; k < 64; k++) {
        float4 b4 = *(const float4*)(Bs + k * 64 + tx * 4);
#pragma unroll
        for (int j = 0; j < 4; j++) {
            float a = As[(ty * 4 + j) * 64 + k];
            acc[j][0] = fmaf(a, b4.x, acc[j][0]);
            acc[j][1] = fmaf(a, b4.y, acc[j][1]);
            acc[j][2] = fmaf(a, b4.z, acc[j][2]);
            acc[j][3] = fmaf(a, b4.w, acc[j][3]);
        }
    }
}

// y = x @ Wm   (no bias/act)
__global__ void k_gemm_y(const float* __restrict__ xw, const float* __restrict__ Wm_i, int N) {
    __shared__ float As[64 * 64], Bs[64 * 64];
    int row0 = blockIdx.x * 64;
    float acc[4][4] = {};
    gemm_load(xw, Wm_i, row0, N, As, Bs);
    int tx = threadIdx.x & 15, ty = threadIdx.x >> 4;
    gemm_compute(As, Bs, tx, ty, acc);
#pragma unroll
    for (int j = 0; j < 4; j++) {
        int gr = row0 + ty * 4 + j;
        if (gr < N)
            *(float4*)(g_y + (size_t)gr * 64 + tx * 4) =
                make_float4(acc[j][0], acc[j][1], acc[j][2], acc[j][3]);
    }
}

// agg[n] = deg>0 ? lrelu(max_src y[src] + bm) : 0   (warp per node, CSR gather)
__global__ void k_agg(const float* __restrict__ bm_i, int N) {
    int wid = threadIdx.x >> 5, lane = threadIdx.x & 31;
    int n = blockIdx.x * 8 + wid;
    if (n >= N) return;
    int off = g_offs[n], d = g_deg[n];
    float m0 = -INFINITY, m1 = -INFINITY;
#pragma unroll 4
    for (int j = 0; j < d; j++) {
        int s = g_src[off + j];
        m0 = fmaxf(m0, g_y[(size_t)s * 64 + lane]);
        m1 = fmaxf(m1, g_y[(size_t)s * 64 + 32 + lane]);
    }
    float a0 = 0.f, a1 = 0.f;
    if (d > 0) {
        a0 = lrelu(m0 + bm_i[lane]);
        a1 = lrelu(m1 + bm_i[32 + lane]);
    }
    g_agg[(size_t)n * 64 + lane] = a0;
    g_agg[(size_t)n * 64 + 32 + lane] = a1;
}

// x = lrelu(x@Wa_x + agg@Wa_a + P[batch] + ba) + x   (in place, two K=64 phases)
__global__ void k_gemm_x(float* __restrict__ xw, const float* __restrict__ Wa_i,
                         const float* __restrict__ ba_i, const int* __restrict__ batch, int N) {
    __shared__ float As[64 * 64], Bs[64 * 64];
    __shared__ float Ps[NGR * 64];
    __shared__ float bas[64];
    int t = threadIdx.x;
#pragma unroll
    for (int it = t; it < NGR * 64; it += 256) Ps[it] = g_P[it];
    if (t < 64) bas[t] = ba_i[t];
    int row0 = blockIdx.x * 64;
    float acc[4][4] = {};
    int tx = t & 15, ty = t >> 4;
    gemm_load(xw, Wa_i, row0, N, As, Bs);              // Wa rows 0..63 (x block)
    gemm_compute(As, Bs, tx, ty, acc);
    gemm_load(g_agg, Wa_i + 128 * 64, row0, N, As, Bs); // Wa rows 128..191 (agg block)
    gemm_compute(As, Bs, tx, ty, acc);
#pragma unroll
    for (int j = 0; j < 4; j++) {
        int gr = row0 + ty * 4 + j;
        if (gr >= N) continue;
        int b = batch[gr];
        float4 xo = *(const float4*)(xw + (size_t)gr * 64 + tx * 4);
        float4 r;
        r.x = lrelu(acc[j][0] + Ps[b * 64 + tx * 4 + 0] + bas[tx * 4 + 0]) + xo.x;
        r.y = lrelu(acc[j][1] + Ps[b * 64 + tx * 4 + 1] + bas[tx * 4 + 1]) + xo.y;
        r.z = lrelu(acc[j][2] + Ps[b * 64 + tx * 4 + 2] + bas[tx * 4 + 2]) + xo.z;
        r.w = lrelu(acc[j][3] + Ps[b * 64 + tx * 4 + 3] + bas[tx * 4 + 3]) + xo.w;
        *(float4*)(xw + (size_t)gr * 64 + tx * 4) = r;
    }
}

// gate = x @ Wgate + bgate ; atomicMax per-graph gmax. 4 lanes per node, 64 nodes/block.
__global__ void k_gate(const float* __restrict__ xw, const float* __restrict__ Wg,
                       const float* __restrict__ bg, const int* __restrict__ batch, int N) {
    __shared__ float wg[64];
    int t = threadIdx.x;
    if (t < 64) wg[t] = Wg[t];
    __syncthreads();
    int lane = t & 31;
    int q = t & 3;
    int r = t >> 2;
    int n = blockIdx.x * 64 + r;
    int nn = min(n, N - 1);
    const float4* xr = (const float4*)(xw + (size_t)nn * 64 + q * 16);
    float s = 0.f;
#pragma unroll
    for (int k = 0; k < 4; k++) {
        float4 v = xr[k];
        int kb = q * 16 + k * 4;
        s = fmaf(v.x, wg[kb + 0], s);
        s = fmaf(v.y, wg[kb + 1], s);
        s = fmaf(v.z, wg[kb + 2], s);
        s = fmaf(v.w, wg[kb + 3], s);
    }
    s += __shfl_xor_sync(0xffffffffu, s, 1);
    s += __shfl_xor_sync(0xffffffffu, s, 2);
    float g = s + bg[0];
    if (n < N && q == 0) g_gate[n] = g;
    float gm = (n < N) ? g : -INFINITY;
    int b = batch[nn];
    int b0 = __shfl_sync(0xffffffffu, b, 0);
    bool uni = __all_sync(0xffffffffu, b == b0);
    if (uni) {
#pragma unroll
        for (int o = 16; o; o >>= 1) gm = fmaxf(gm, __shfl_xor_sync(0xffffffffu, gm, o));
        if (lane == 0) atomicMax(&g_gmax[b0], ordInt(gm));
    } else {
        if (q == 0 && n < N) atomicMax(&g_gmax[b], ordInt(gm));
    }
}

// feat = lrelu(x @ Wfeat + bfeat)
__global__ void k_gemm_feat(const float* __restrict__ xw, const float* __restrict__ Wf_i,
                            const float* __restrict__ bf_i, int N) {
    __shared__ float As[64 * 64], Bs[64 * 64];
    __shared__ float bfs[64];
    int t = threadIdx.x;
    if (t < 64) bfs[t] = bf_i[t];
    int row0 = blockIdx.x * 64;
    float acc[4][4] = {};
    gemm_load(xw, Wf_i, row0, N, As, Bs);
    int tx = t & 15, ty = t >> 4;
    gemm_compute(As, Bs, tx, ty, acc);
#pragma unroll
    for (int j = 0; j < 4; j++) {
        int gr = row0 + ty * 4 + j;
        if (gr >= N) continue;
        float4 r;
        r.x = lrelu(acc[j][0] + bfs[tx * 4 + 0]);
        r.y = lrelu(acc[j][1] + bfs[tx * 4 + 1]);
        r.z = lrelu(acc[j][2] + bfs[tx * 4 + 2]);
        r.w = lrelu(acc[j][3] + bfs[tx * 4 + 3]);
        *(float4*)(g_feat + (size_t)gr * 64 + tx * 4) = r;
    }
}

// accumulate denom = sum e, numvec = sum e*feat (run-length flush, batch_ind sorted)
__global__ void k_passB(const int* __restrict__ batch, int N) {
    int tx = threadIdx.x;  // 0..63 feature
    int ty = threadIdx.y;  // 0..3
    int base = blockIdx.x * 256;
    int nend = min(base + 256, N);
    float acc = 0.f, accd = 0.f;
    int gcur = -1;
    for (int n = base + ty; n < nend; n += 4) {
        int b = batch[n];
        if (b != gcur) {
            if (gcur >= 0) {
                atomicAdd(&g_numvec[gcur * 64 + tx], acc);
                if (tx == 0) atomicAdd(&g_denom[gcur], accd);
            }
            gcur = b; acc = 0.f; accd = 0.f;
        }
        float e = expf(g_gate[n] - ordFloat(g_gmax[b]));
        acc = fmaf(e, g_feat[(size_t)n * 64 + tx], acc);
        accd += e;
    }
    if (gcur >= 0) {
        atomicAdd(&g_numvec[gcur * 64 + tx], acc);
        if (tx == 0) atomicAdd(&g_denom[gcur], accd);
    }
}

// x_global = lrelu([xg_pool | x_global] @ Wt + bt) + x_global. 1 block, 1024 threads.
__global__ void k_global(float* __restrict__ xglob, const float* __restrict__ Wt_i,
                         const float* __restrict__ bt_i) {
    __shared__ float cat[NGR * 128];
    int t = threadIdx.x;
    int g = t >> 6, c = t & 63;
    cat[g * 128 + c] = g_numvec[g * 64 + c] / g_denom[g];
    cat[g * 128 + 64 + c] = xglob[g * 64 + c];
    __syncthreads();
    float s = bt_i[c];
#pragma unroll 8
    for (int k = 0; k < 128; k++) s = fmaf(cat[g * 128 + k], Wt_i[k * 64 + c], s);
    s = lrelu(s) + cat[g * 128 + 64 + c];
    xglob[g * 64 + c] = s;
}

// ---------------- launch ----------------
extern "C" void kernel_launch(void* const* d_in, const int* in_sizes, int n_in,
                              void* d_out, int out_size) {
    const float* x       = (const float*)d_in[0];
    const float* xglobal = (const float*)d_in[1];
    const int*   ei      = (const int*)d_in[3];
    const int*   batch   = (const int*)d_in[4];
    int base = (in_sizes[5] == 1) ? 6 : 5;  // num_graphs scalar may or may not be passed
    const float* Wm    = (const float*)d_in[base + 0];
    const float* bm    = (const float*)d_in[base + 1];
    const float* Wa    = (const float*)d_in[base + 2];
    const float* ba    = (const float*)d_in[base + 3];
    const float* Wgate = (const float*)d_in[base + 4];
    const float* bgate = (const float*)d_in[base + 5];
    const float* Wfeat = (const float*)d_in[base + 6];
    const float* bfeat = (const float*)d_in[base + 7];
    const float* Wt    = (const float*)d_in[base + 8];
    const float* bt    = (const float*)d_in[base + 9];

    int N = in_sizes[0] / DD;
    int E = in_sizes[3] / 2;
    float* out = (float*)d_out;
    float* xw  = out;                      // working x lives in d_out
    float* xg  = out + (size_t)N * DD;     // working x_global lives in d_out

    int tot = N * DD + NGR * DD;
    k_copy_init<<<(tot + 255) / 256, 256>>>(x, xglobal, out, N);
    k_csr_zero<<<(N + 255) / 256, 256>>>(N);
    k_deg<<<(E + 255) / 256, 256>>>(ei, E);
    k_alloc<<<(N + 255) / 256, 256>>>(N);
    k_fill<<<(E + 255) / 256, 256>>>(ei, E);

    int gb = (N + 63) / 64;
    dim3 pb(64, 4);
    for (int i = 0; i < 4; i++) {
        k_init_step<<<1, 1024>>>(xg, Wa + ((size_t)i * 192 + 64) * 64);
        k_gemm_y<<<gb, 256>>>(xw, Wm + (size_t)i * 64 * 64, N);
        k_agg<<<(N + 7) / 8, 256>>>(bm + i * 64, N);
        k_gemm_x<<<gb, 256>>>(xw, Wa + (size_t)i * 192 * 64, ba + i * 64, batch, N);
        k_gate<<<gb, 256>>>(xw, Wgate + i * 64, bgate + i, batch, N);
        k_gemm_feat<<<gb, 256>>>(xw, Wfeat + (size_t)i * 64 * 64, bfeat + i * 64, N);
        k_passB<<<(N + 255) / 256, pb>>>(batch, N);
        k_global<<<1, 1024>>>(xg, Wt + (size_t)i * 128 * 64, bt + i * 64);
    }
}